// round 2
// baseline (speedup 1.0000x reference)
#include <cuda_runtime.h>
#include <math.h>

#define N_NODES 50000
#define N_EDGES 640000
#define IN_DIM 5
#define HID 128
#define NUM_GRAPHS 512

// ---------------- device scratch (static, no allocation) ----------------
__device__ __align__(16) float g_agg [N_NODES * HID];
__device__ __align__(16) float g_h0  [N_NODES * HID];
__device__ __align__(16) float g_h1  [N_NODES * HID];
__device__ __align__(16) float g_agg0[N_NODES * IN_DIM];
__device__ float g_pooled[NUM_GRAPHS * HID];
__device__ int   g_deg   [N_NODES];
__device__ int   g_rowptr[N_NODES + 1];
__device__ int   g_cursor[N_NODES];
__device__ int   g_csr_src[N_EDGES];
__device__ int   g_cnt   [NUM_GRAPHS];

// ---------------- zero init ----------------
__global__ void k_zero() {
    int i = blockIdx.x * blockDim.x + threadIdx.x;
    if (i < N_NODES) g_deg[i] = 0;
    if (i < NUM_GRAPHS * HID) g_pooled[i] = 0.0f;
    if (i < NUM_GRAPHS) g_cnt[i] = 0;
}

// ---------------- CSR build ----------------
__global__ void k_hist(const int* __restrict__ ei) {
    int e = blockIdx.x * blockDim.x + threadIdx.x;
    if (e < N_EDGES) atomicAdd(&g_deg[ei[N_EDGES + e]], 1);
}

__global__ void k_scan() {
    __shared__ int sums[1024];
    int t = threadIdx.x;
    const int CH = (N_NODES + 1023) / 1024;   // 49
    int start = t * CH;
    int end = start + CH; if (end > N_NODES) end = N_NODES;
    int s = 0;
    for (int i = start; i < end; i++) s += g_deg[i];
    sums[t] = s;
    __syncthreads();
    for (int off = 1; off < 1024; off <<= 1) {
        int v = (t >= off) ? sums[t - off] : 0;
        __syncthreads();
        sums[t] += v;
        __syncthreads();
    }
    int base = (t == 0) ? 0 : sums[t - 1];
    for (int i = start; i < end; i++) {
        int d = g_deg[i];
        g_rowptr[i] = base;
        g_cursor[i] = base;
        base += d;
    }
    if (t == 1023) g_rowptr[N_NODES] = sums[1023];
}

__global__ void k_scatter(const int* __restrict__ ei) {
    int e = blockIdx.x * blockDim.x + threadIdx.x;
    if (e < N_EDGES) {
        int d = ei[N_EDGES + e];
        int p = atomicAdd(&g_cursor[d], 1);
        g_csr_src[p] = ei[e];
    }
}

__global__ void k_cnt(const int* __restrict__ batch) {
    int i = blockIdx.x * blockDim.x + threadIdx.x;
    if (i < N_NODES) atomicAdd(&g_cnt[batch[i]], 1);
}

// ---------------- layer 0 (IN_DIM = 5) ----------------
__global__ void k_agg0(const float* __restrict__ x) {
    int n = blockIdx.x * blockDim.x + threadIdx.x;
    if (n >= N_NODES) return;
    float s0 = 0.f, s1 = 0.f, s2 = 0.f, s3 = 0.f, s4 = 0.f;
    int beg = g_rowptr[n], end = g_rowptr[n + 1];
    for (int j = beg; j < end; j++) {
        const float* xr = x + (size_t)g_csr_src[j] * IN_DIM;
        s0 += xr[0]; s1 += xr[1]; s2 += xr[2]; s3 += xr[3]; s4 += xr[4];
    }
    float* o = g_agg0 + (size_t)n * IN_DIM;
    o[0] = s0; o[1] = s1; o[2] = s2; o[3] = s3; o[4] = s4;
}

__global__ void k_h0(const float* __restrict__ x,
                     const float* __restrict__ Wrel, const float* __restrict__ brel,
                     const float* __restrict__ Wroot) {
    __shared__ float sa[IN_DIM], sx[IN_DIM];
    int n = blockIdx.x;
    int c = threadIdx.x;              // 128 threads
    if (c < IN_DIM) {
        sa[c] = g_agg0[(size_t)n * IN_DIM + c];
        sx[c] = x[(size_t)n * IN_DIM + c];
    }
    __syncthreads();
    float v = brel[c];
#pragma unroll
    for (int k = 0; k < IN_DIM; k++) {
        v = fmaf(sa[k], Wrel[k * HID + c], v);
        v = fmaf(sx[k], Wroot[k * HID + c], v);
    }
    g_h0[(size_t)n * HID + c] = fmaxf(v, 0.0f);
}

// ---------------- edge aggregation, warp per node (128-dim) ----------------
// phase 0: gather g_h0 -> g_agg ; phase 1: gather g_h1 -> g_agg
__global__ void k_gather(int phase) {
    int gwarp = (blockIdx.x * blockDim.x + threadIdx.x) >> 5;
    int lane = threadIdx.x & 31;
    if (gwarp >= N_NODES) return;
    const float4* h = (const float4*)(phase == 0 ? g_h0 : g_h1);
    float4 acc = make_float4(0.f, 0.f, 0.f, 0.f);
    int beg = g_rowptr[gwarp], end = g_rowptr[gwarp + 1];
    for (int j = beg; j < end; j++) {
        int s = g_csr_src[j];
        float4 v = __ldg(&h[(size_t)s * (HID / 4) + lane]);
        acc.x += v.x; acc.y += v.y; acc.z += v.z; acc.w += v.w;
    }
    ((float4*)g_agg)[(size_t)gwarp * (HID / 4) + lane] = acc;
}

// ---------------- fused GEMM: out = act(agg @ Wrel + b + h @ Wroot) ----------------
// POOL==0: H = g_h0, store relu result into g_h1
// POOL==1: H = g_h1, no store; atomicAdd into g_pooled[batch[row]]
template <int RELU, int POOL>
__global__ __launch_bounds__(256)
void k_gemm(const float* __restrict__ Wrel, const float* __restrict__ Wroot,
            const float* __restrict__ bias, const int* __restrict__ batch) {
    __shared__ float As[64][32];
    __shared__ float Hs[64][32];
    __shared__ float Wr[32][HID];
    __shared__ float Wo[32][HID];

    const int tid = threadIdx.x;
    const int tx = tid & 31;          // 32 col groups -> 4 cols each
    const int ty = tid >> 5;          // 8 row groups  -> 8 rows each
    const int row0 = blockIdx.x * 64;

    const float* A = g_agg;
    const float* H = POOL ? g_h1 : g_h0;

    float acc[8][4];
#pragma unroll
    for (int i = 0; i < 8; i++)
#pragma unroll
        for (int j = 0; j < 4; j++) acc[i][j] = 0.0f;

    for (int k0 = 0; k0 < HID; k0 += 32) {
        // load A/H tiles: 64 rows x 32 cols, 512 float4 total, 2 per thread
#pragma unroll
        for (int l = 0; l < 2; l++) {
            int idx = tid + l * 256;
            int r = idx >> 3, c4 = idx & 7;
            int gr = row0 + r;
            float4 av = make_float4(0.f, 0.f, 0.f, 0.f);
            float4 hv = av;
            if (gr < N_NODES) {
                av = *(const float4*)(A + (size_t)gr * HID + k0 + c4 * 4);
                hv = *(const float4*)(H + (size_t)gr * HID + k0 + c4 * 4);
            }
            *(float4*)&As[r][c4 * 4] = av;
            *(float4*)&Hs[r][c4 * 4] = hv;
        }
        // load W tiles: 32 x 128 each, 1024 float4 each, 4 per thread
#pragma unroll
        for (int l = 0; l < 4; l++) {
            int idx = tid + l * 256;
            int kk = idx >> 5, c4 = idx & 31;
            *(float4*)&Wr[kk][c4 * 4] = *(const float4*)(Wrel + (size_t)(k0 + kk) * HID + c4 * 4);
            *(float4*)&Wo[kk][c4 * 4] = *(const float4*)(Wroot + (size_t)(k0 + kk) * HID + c4 * 4);
        }
        __syncthreads();

#pragma unroll 4
        for (int kk = 0; kk < 32; kk++) {
            float4 wr = *(float4*)&Wr[kk][tx * 4];
            float4 wo = *(float4*)&Wo[kk][tx * 4];
#pragma unroll
            for (int i = 0; i < 8; i++) {
                float a = As[ty * 8 + i][kk];
                float h = Hs[ty * 8 + i][kk];
                acc[i][0] = fmaf(a, wr.x, acc[i][0]); acc[i][0] = fmaf(h, wo.x, acc[i][0]);
                acc[i][1] = fmaf(a, wr.y, acc[i][1]); acc[i][1] = fmaf(h, wo.y, acc[i][1]);
                acc[i][2] = fmaf(a, wr.z, acc[i][2]); acc[i][2] = fmaf(h, wo.z, acc[i][2]);
                acc[i][3] = fmaf(a, wr.w, acc[i][3]); acc[i][3] = fmaf(h, wo.w, acc[i][3]);
            }
        }
        __syncthreads();
    }

    float4 bv = *(const float4*)(bias + tx * 4);
#pragma unroll
    for (int i = 0; i < 8; i++) {
        int gr = row0 + ty * 8 + i;
        if (gr >= N_NODES) break;
        float v0 = acc[i][0] + bv.x;
        float v1 = acc[i][1] + bv.y;
        float v2 = acc[i][2] + bv.z;
        float v3 = acc[i][3] + bv.w;
        if (RELU) {
            v0 = fmaxf(v0, 0.f); v1 = fmaxf(v1, 0.f);
            v2 = fmaxf(v2, 0.f); v3 = fmaxf(v3, 0.f);
        }
        if (!POOL) {
            *(float4*)&g_h1[(size_t)gr * HID + tx * 4] = make_float4(v0, v1, v2, v3);
        } else {
            int g = batch[gr];
            float* p = &g_pooled[(size_t)g * HID + tx * 4];
            atomicAdd(p + 0, v0);
            atomicAdd(p + 1, v1);
            atomicAdd(p + 2, v2);
            atomicAdd(p + 3, v3);
        }
    }
}

// ---------------- final: mean pool -> linear -> sigmoid ----------------
__global__ void k_final(const float* __restrict__ Wlin, const float* __restrict__ blin,
                        float* __restrict__ out) {
    int g = blockIdx.x;
    int t = threadIdx.x;              // 128
    float cnt = fmaxf((float)g_cnt[g], 1.0f);
    float v = g_pooled[(size_t)g * HID + t] * (1.0f / cnt) * Wlin[t];
#pragma unroll
    for (int off = 16; off > 0; off >>= 1)
        v += __shfl_xor_sync(0xffffffffu, v, off);
    __shared__ float ws[4];
    if ((t & 31) == 0) ws[t >> 5] = v;
    __syncthreads();
    if (t == 0) {
        float s = ws[0] + ws[1] + ws[2] + ws[3] + blin[0];
        out[g] = 1.0f / (1.0f + expf(-s));
    }
}

// ---------------- launch ----------------
extern "C" void kernel_launch(void* const* d_in, const int* in_sizes, int n_in,
                              void* d_out, int out_size) {
    const float* x      = (const float*)d_in[0];
    const int*   ei     = (const int*)d_in[1];
    const int*   batch  = (const int*)d_in[2];
    const float* Wrel0  = (const float*)d_in[3];
    const float* brel0  = (const float*)d_in[4];
    const float* Wroot0 = (const float*)d_in[5];
    const float* Wrel1  = (const float*)d_in[6];
    const float* brel1  = (const float*)d_in[7];
    const float* Wroot1 = (const float*)d_in[8];
    const float* Wrel2  = (const float*)d_in[9];
    const float* brel2  = (const float*)d_in[10];
    const float* Wroot2 = (const float*)d_in[11];
    const float* Wlin   = (const float*)d_in[12];
    const float* blin   = (const float*)d_in[13];
    float* out = (float*)d_out;

    k_zero<<<(NUM_GRAPHS * HID + 255) / 256, 256>>>();
    k_hist<<<(N_EDGES + 255) / 256, 256>>>(ei);
    k_scan<<<1, 1024>>>();
    k_scatter<<<(N_EDGES + 255) / 256, 256>>>(ei);
    k_cnt<<<(N_NODES + 255) / 256, 256>>>(batch);

    // layer 0
    k_agg0<<<(N_NODES + 255) / 256, 256>>>(x);
    k_h0<<<N_NODES, HID>>>(x, Wrel0, brel0, Wroot0);

    // layer 1
    k_gather<<<(N_NODES * 32 + 255) / 256, 256>>>(0);
    k_gemm<1, 0><<<(N_NODES + 63) / 64, 256>>>(Wrel1, Wroot1, brel1, batch);

    // layer 2 (+ fused pooling accumulate)
    k_gather<<<(N_NODES * 32 + 255) / 256, 256>>>(1);
    k_gemm<0, 1><<<(N_NODES + 63) / 64, 256>>>(Wrel2, Wroot2, brel2, batch);

    // head
    k_final<<<NUM_GRAPHS, HID>>>(Wlin, blin, out);
}